// round 15
// baseline (speedup 1.0000x reference)
#include <cuda_runtime.h>

// BiRealConv2d: y = conv3x3(sign(x), scale_o * sign(w)), pad 1, stride 1.
// Weights here are uniform[0,1)*1e-3 (non-negative) -> sign(w)=+1 a.s., so
// y[n,o,h,w] = scale_o * boxsum3x3(sum_c sign(x))[n,h,w].
// Blocks 0..127 record any weight with sign != +1 at deterministic slots;
// the write phases patch those contributions inline -> exact for any data.
//
// ONE kernel, grid 448 (14 8-row tiles x 32 images), 288 threads. Each block
// alternates read/write quanta over two half-tiles:
//   readA (T rows -1..4) -> writeB (out rows 0..3, all 128 ch)
//   readC (T rows  5..8) -> writeD (out rows 4..7, all 128 ch)
// so chip-wide, desynchronized blocks keep HBM reads AND writes in flight for
// most of the kernel (mixed-direction traffic measured faster than either
// pure stream). Write quanta use 224 threads = 112 positions x 2 channel
// halves (64 coalesced STG.128 each). Weight scales are produced by blocks
// 0..127 before tile work and consumed behind a monotonic counter
// (graph-replay safe; all 448 blocks co-resident -> spin cannot deadlock).

#define N_    32
#define C_    128
#define H_    112
#define W_    112
#define HW_   (H_ * W_)       // 12544
#define P4_   (HW_ / 4)       // 3136
#define W4_   (W_ / 4)        // 28
#define OC_   128
#define WPO_  (C_ * 9)        // 1152
#define WPO4_ (WPO_ / 4)      // 288

#define TPB   288             // 9 warps
#define RH    8               // output rows per tile
#define TPI   (H_ / RH)       // 14 tiles per image
#define NTILE (N_ * TPI)      // 448 blocks

__device__ float g_scale[OC_];
__device__ int   g_na[OC_];
__device__ signed char g_acode[OC_ * WPO_];   // 0 normal, -1 zero, -2 negative
__device__ unsigned long long g_epoch;        // monotonic across launches
__device__ unsigned long long g_wdone;        // +=OC_ per launch

__device__ __forceinline__ float sgnf(float v) {
    return (float)((v > 0.f) - (v < 0.f));
}

__global__ void __launch_bounds__(TPB, 4)
fused(const float* __restrict__ x, const float* __restrict__ w,
      float* __restrict__ y) {
    const int t    = threadIdx.x;
    const int tile = blockIdx.x;
    const int n    = tile / TPI;
    const int h0   = (tile - n * TPI) * RH;

    __shared__ float Ts[(RH + 2) * W_];   // T rows h0-1 .. h0+RH (idx 0..9)
    __shared__ float s_scale[OC_];
    __shared__ int   s_na[OC_];
    __shared__ float red[TPB];
    __shared__ unsigned long long se;

    if (t == 0) se = atomicAdd(&g_epoch, 1ULL) / NTILE + 1ULL;
    __syncthreads();
    const unsigned long long e = se;

    // ---- producer duty: blocks 0..127 emit scale/anomaly data for channel o
    if (tile < OC_) {
        const int o = tile;
        float4 v = reinterpret_cast<const float4*>(w + o * WPO_)[t];  // WPO4_==TPB
        const float vv[4] = {v.x, v.y, v.z, v.w};
        float s = 0.f;
        int   na = 0;
#pragma unroll
        for (int q = 0; q < 4; ++q) {
            s += fabsf(vv[q]);
            signed char code = 0;
            if (vv[q] <= 0.f) { code = (vv[q] < 0.f) ? -2 : -1; na = 1; }
            g_acode[o * WPO_ + t * 4 + q] = code;
        }
        red[t] = s;
        int any = __syncthreads_or(na);
        if (t < 144) red[t] += red[t + 144];
        __syncthreads();
        if (t < 72)  red[t] += red[t + 72];
        __syncthreads();
        if (t < 36)  red[t] += red[t + 36];
        __syncthreads();
        if (t < 18)  red[t] += red[t + 18];
        __syncthreads();
        if (t < 9)   red[t] += red[t + 9];
        __syncthreads();
        if (t == 0) {
            float tot = 0.f;
#pragma unroll
            for (int q = 0; q < 9; ++q) tot += red[q];
            g_scale[o] = tot / (float)WPO_;
            g_na[o]    = any;
            __threadfence();
            atomicAdd(&g_wdone, 1ULL);
        }
        __syncthreads();
    }

    const float4* xb = reinterpret_cast<const float4*>(x) + (size_t)n * (C_ * P4_);

    // ---- phase A: T rows 0..5 (gh = h0-1 .. h0+4), 168 tasks, one round
    if (t < 6 * W4_) {
        int row = t / W4_;
        int c4  = t - row * W4_;
        int gh  = h0 - 1 + row;
        float4 acc = make_float4(0.f, 0.f, 0.f, 0.f);
        if ((unsigned)gh < (unsigned)H_) {
            const float4* p = xb + gh * W4_ + c4;
#pragma unroll 8
            for (int c = 0; c < C_; ++c) {
                float4 v = p[(size_t)c * P4_];
                acc.x += sgnf(v.x); acc.y += sgnf(v.y);
                acc.z += sgnf(v.z); acc.w += sgnf(v.w);
            }
        }
        reinterpret_cast<float4*>(Ts)[t] = acc;
    }
    __syncthreads();

    // ---- weights ready? (zero wait in practice). Stage scales in smem.
    if (t == 0) {
        while (atomicAdd(&g_wdone, 0ULL) < (unsigned long long)OC_ * e)
            __nanosleep(64);
    }
    __syncthreads();
    int myna = (t < OC_) ? g_na[t] : 0;
    if (t < OC_) { s_scale[t] = g_scale[t]; s_na[t] = myna; }
    const int any_na = __syncthreads_or(myna);

    // ================= write half-tile macro body =================
#define WRITE_HALF(RBASE)                                                     \
    if (t < 224) {                                                            \
        const int half = t / 112;            /* channel half */               \
        const int pos  = t - half * 112;                                      \
        const int r    = (RBASE) + pos / W4_;                                 \
        const int c4   = pos % W4_;                                           \
        float4 acc = make_float4(0.f, 0.f, 0.f, 0.f);                         \
        _Pragma("unroll")                                                     \
        for (int rr = r; rr < r + 3; ++rr) {                                  \
            const float* row = Ts + rr * W_;                                  \
            float4 cv = reinterpret_cast<const float4*>(row)[c4];             \
            float  l  = (c4 > 0)       ? row[c4 * 4 - 1] : 0.f;               \
            float  rg = (c4 < W4_ - 1) ? row[c4 * 4 + 4] : 0.f;               \
            acc.x += l    + cv.x + cv.y;                                      \
            acc.y += cv.x + cv.y + cv.z;                                      \
            acc.z += cv.y + cv.z + cv.w;                                      \
            acc.w += cv.z + cv.w + rg;                                        \
        }                                                                     \
        const int lh = h0 + r;                                                \
        float4* y4 = reinterpret_cast<float4*>(y)                             \
                   + (size_t)n * (OC_ * P4_) + (size_t)half * 64 * P4_        \
                   + lh * W4_ + c4;                                           \
        if (!any_na) {                                                        \
            _Pragma("unroll 4")                                               \
            for (int j = 0; j < 64; ++j) {                                    \
                float sc = s_scale[half * 64 + j];                            \
                __stcs(y4 + (size_t)j * P4_,                                  \
                       make_float4(sc * acc.x, sc * acc.y,                    \
                                   sc * acc.z, sc * acc.w));                  \
            }                                                                 \
        } else {                                                              \
            for (int j = 0; j < 64; ++j) {                                    \
                const int o = half * 64 + j;                                  \
                float sc = s_scale[o];                                        \
                float4 val = make_float4(sc * acc.x, sc * acc.y,              \
                                         sc * acc.z, sc * acc.w);             \
                if (s_na[o] != 0) {                                           \
                    for (int f = 0; f < WPO_; ++f) {                          \
                        int code = (int)g_acode[o * WPO_ + f];                \
                        if (code == 0) continue;                              \
                        int c  = f / 9, kk = f % 9;                           \
                        int dh = kk / 3 - 1, dw = kk % 3 - 1;                 \
                        int hh = lh + dh;                                     \
                        if ((unsigned)hh >= (unsigned)H_) continue;           \
                        const float* xr = x + ((size_t)n * C_ + c) * HW_      \
                                        + hh * W_;                            \
                        _Pragma("unroll")                                     \
                        for (int q = 0; q < 4; ++q) {                         \
                            int ww = c4 * 4 + q + dw;                         \
                            if ((unsigned)ww >= (unsigned)W_) continue;       \
                            float add = sc * (float)code * sgnf(xr[ww]);      \
                            if (q == 0) val.x += add;                         \
                            else if (q == 1) val.y += add;                    \
                            else if (q == 2) val.z += add;                    \
                            else val.w += add;                                \
                        }                                                     \
                    }                                                         \
                }                                                             \
                __stcs(y4 + (size_t)j * P4_, val);                            \
            }                                                                 \
        }                                                                     \
    }
    // ==============================================================

    // ---- phase B: write out rows 0..3 (box-sum uses Ts rows 0..5)
    WRITE_HALF(0)
    __syncthreads();

    // ---- phase C: T rows 6..9 (gh = h0+5 .. h0+8), 112 tasks
    if (t < 4 * W4_) {
        int row = 6 + t / W4_;
        int c4  = t % W4_;
        int gh  = h0 - 1 + row;
        float4 acc = make_float4(0.f, 0.f, 0.f, 0.f);
        if ((unsigned)gh < (unsigned)H_) {
            const float4* p = xb + gh * W4_ + c4;
#pragma unroll 8
            for (int c = 0; c < C_; ++c) {
                float4 v = p[(size_t)c * P4_];
                acc.x += sgnf(v.x); acc.y += sgnf(v.y);
                acc.z += sgnf(v.z); acc.w += sgnf(v.w);
            }
        }
        reinterpret_cast<float4*>(Ts)[6 * W4_ + t] = acc;
    }
    __syncthreads();

    // ---- phase D: write out rows 4..7 (box-sum uses Ts rows 4..9)
    WRITE_HALF(4)
}

extern "C" void kernel_launch(void* const* d_in, const int* in_sizes, int n_in,
                              void* d_out, int out_size) {
    const float* x = (const float*)d_in[0];
    const float* w = (const float*)d_in[1];
    float* y = (float*)d_out;
    fused<<<NTILE, TPB>>>(x, w, y);
}

// round 17
// speedup vs baseline: 1.2479x; 1.2479x over previous
#include <cuda_runtime.h>

// BiRealConv2d: y = conv3x3(sign(x), scale_o * sign(w)), pad 1, stride 1.
// Weights here are uniform[0,1)*1e-3 (non-negative) -> sign(w)=+1 a.s., so
// y[n,o,h,w] = scale_o * boxsum3x3(sum_c sign(x))[n,h,w].
// Blocks 0..127 record any weight with sign != +1 at deterministic slots;
// phase 3 patches those contributions inline -> exact for arbitrary data.
//
// ONE kernel, 288 threads/block. Each block owns (image, 8 output rows):
// channel-sum T (+halo) into smem -- 280 tasks over 288 threads = ONE
// balanced round -- then per-thread 3x3 box-sum in registers and
// broadcast-store of all 128 output channels. Weight scales are produced by
// blocks 0..127 before their tile work and consumed at phase 3 behind a
// monotonic counter (graph-replay safe; producers never wait and all blocks
// are co-resident, so the wait cannot deadlock; it is ~zero in practice).

#define N_    32
#define C_    128
#define H_    112
#define W_    112
#define HW_   (H_ * W_)       // 12544
#define P4_   (HW_ / 4)       // 3136
#define W4_   (W_ / 4)        // 28
#define OC_   128
#define WPO_  (C_ * 9)        // 1152
#define WPO4_ (WPO_ / 4)      // 288

#define TPB   288             // 9 warps
#define RH    8               // output rows per tile
#define TPI   (H_ / RH)       // 14 tiles per image
#define NTILE (N_ * TPI)      // 448 blocks
#define TT    ((RH + 2) * W4_)  // 280 T float4 tasks  (<= TPB, one round)
#define ST    (RH * W4_)        // 224 box-sum positions

__device__ float g_scale[OC_];
__device__ int   g_na[OC_];
__device__ signed char g_acode[OC_ * WPO_];   // 0 normal, -1 zero, -2 negative
__device__ unsigned long long g_epoch;        // monotonic across launches
__device__ unsigned long long g_wdone;        // +=OC_ per launch

__device__ __forceinline__ float sgnf(float v) {
    return (float)((v > 0.f) - (v < 0.f));
}

__global__ void __launch_bounds__(TPB, 4)
fused(const float* __restrict__ x, const float* __restrict__ w,
      float* __restrict__ y) {
    const int t    = threadIdx.x;
    const int tile = blockIdx.x;
    const int n    = tile / TPI;
    const int h0   = (tile - n * TPI) * RH;

    __shared__ float Ts[(RH + 2) * W_];   // channel-sum rows h0-1 .. h0+RH
    __shared__ float s_scale[OC_];
    __shared__ int   s_na[OC_];
    __shared__ float red[TPB];
    __shared__ unsigned long long se;

    if (t == 0) se = atomicAdd(&g_epoch, 1ULL) / NTILE + 1ULL;
    __syncthreads();
    const unsigned long long e = se;

    // ---- producer duty: blocks 0..127 emit scale/anomaly data for channel o
    if (tile < OC_) {
        const int o = tile;
        // exactly one float4 per thread (WPO4_ == TPB)
        float4 v = reinterpret_cast<const float4*>(w + o * WPO_)[t];
        const float vv[4] = {v.x, v.y, v.z, v.w};
        float s = 0.f;
        int   na = 0;
#pragma unroll
        for (int q = 0; q < 4; ++q) {
            s += fabsf(vv[q]);
            signed char code = 0;
            if (vv[q] <= 0.f) { code = (vv[q] < 0.f) ? -2 : -1; na = 1; }
            g_acode[o * WPO_ + t * 4 + q] = code;
        }
        red[t] = s;
        int any = __syncthreads_or(na);
        // deterministic tree reduce over 288 = 2*144
        if (t < 144) red[t] += red[t + 144];
        __syncthreads();
        if (t < 72)  red[t] += red[t + 72];
        __syncthreads();
        if (t < 36)  red[t] += red[t + 36];
        __syncthreads();
        if (t < 18)  red[t] += red[t + 18];
        __syncthreads();
        if (t < 9)   red[t] += red[t + 9];
        __syncthreads();
        if (t == 0) {
            float tot = 0.f;
#pragma unroll
            for (int q = 0; q < 9; ++q) tot += red[q];
            g_scale[o] = tot / (float)WPO_;
            g_na[o]    = any;
            __threadfence();
            atomicAdd(&g_wdone, 1ULL);
        }
        __syncthreads();
    }

    // ---- phase 1: channel-sum rows h0-1 .. h0+RH into smem (one round)
    if (t < TT) {
        int row = t / W4_;                // 0..RH+1
        int c4  = t - row * W4_;
        int gh  = h0 - 1 + row;
        float4 acc = make_float4(0.f, 0.f, 0.f, 0.f);
        if ((unsigned)gh < (unsigned)H_) {
            const float4* p = reinterpret_cast<const float4*>(x)
                            + (size_t)n * (C_ * P4_) + gh * W4_ + c4;
#pragma unroll 8
            for (int c = 0; c < C_; ++c) {
                float4 v = p[(size_t)c * P4_];
                acc.x += sgnf(v.x); acc.y += sgnf(v.y);
                acc.z += sgnf(v.z); acc.w += sgnf(v.w);
            }
        }
        reinterpret_cast<float4*>(Ts)[t] = acc;
    }
    __syncthreads();

    // ---- weights ready? (zero wait in practice). Stage scales in smem.
    if (t == 0) {
        while (atomicAdd(&g_wdone, 0ULL) < (unsigned long long)OC_ * e)
            __nanosleep(64);
    }
    __syncthreads();
    if (t < OC_) { s_scale[t] = g_scale[t]; s_na[t] = g_na[t]; }
    __syncthreads();

    // ---- phase 2+3: per-thread box-sum (registers), then broadcast-store
    if (t < ST) {
        const int r  = t / W4_;
        const int c4 = t - r * W4_;
        float4 acc = make_float4(0.f, 0.f, 0.f, 0.f);
#pragma unroll
        for (int rr = r; rr < r + 3; ++rr) {
            const float* row = Ts + rr * W_;
            float4 c = reinterpret_cast<const float4*>(row)[c4];
            float  l  = (c4 > 0)        ? row[c4 * 4 - 1] : 0.f;
            float  rg = (c4 < W4_ - 1)  ? row[c4 * 4 + 4] : 0.f;
            acc.x += l   + c.x + c.y;
            acc.y += c.x + c.y + c.z;
            acc.z += c.y + c.z + c.w;
            acc.w += c.z + c.w + rg;
        }

        float4* y4 = reinterpret_cast<float4*>(y)
                   + (size_t)n * (OC_ * P4_) + (h0 + r) * W4_ + c4;
#pragma unroll 4
        for (int o = 0; o < OC_; ++o) {
            float sc = s_scale[o];
            float4 val = make_float4(sc * acc.x, sc * acc.y,
                                     sc * acc.z, sc * acc.w);
            if (s_na[o] != 0) {
                // exact sparse correction: scale * (sign(w)-1) * sign(x)
                const int h = h0 + r;
                for (int f = 0; f < WPO_; ++f) {
                    int code = (int)g_acode[o * WPO_ + f];
                    if (code == 0) continue;
                    int c  = f / 9, kk = f % 9;
                    int dh = kk / 3 - 1, dw = kk % 3 - 1;
                    int hh = h + dh;
                    if ((unsigned)hh >= (unsigned)H_) continue;
                    const float* xr = x + ((size_t)n * C_ + c) * HW_ + hh * W_;
#pragma unroll
                    for (int q = 0; q < 4; ++q) {
                        int ww = c4 * 4 + q + dw;
                        if ((unsigned)ww >= (unsigned)W_) continue;
                        float add = sc * (float)code * sgnf(xr[ww]);
                        if (q == 0) val.x += add;
                        else if (q == 1) val.y += add;
                        else if (q == 2) val.z += add;
                        else val.w += add;
                    }
                }
            }
            __stcs(y4 + (size_t)o * P4_, val);
        }
    }
}

extern "C" void kernel_launch(void* const* d_in, const int* in_sizes, int n_in,
                              void* d_out, int out_size) {
    const float* x = (const float*)d_in[0];
    const float* w = (const float*)d_in[1];
    float* y = (float*)d_out;
    fused<<<NTILE, TPB>>>(x, w, y);
}